// round 14
// baseline (speedup 1.0000x reference)
#include <cuda_runtime.h>
#include <cuda_fp16.h>

#define HID 64
#define MAXN 500000
#define MAXE 800000

typedef unsigned long long ull;
typedef unsigned int uint;

__device__ __forceinline__ ull pack2(float lo, float hi) {
    ull r; asm("mov.b64 %0, {%1,%2};" : "=l"(r) : "f"(lo), "f"(hi)); return r;
}
__device__ __forceinline__ void unpack2(ull v, float& lo, float& hi) {
    asm("mov.b64 {%0,%1}, %2;" : "=f"(lo), "=f"(hi) : "l"(v));
}
__device__ __forceinline__ void fma2(ull& d, ull a, ull b) {
    asm("fma.rn.f32x2 %0, %1, %2, %0;" : "+l"(d) : "l"(a), "l"(b));
}
// split floats x0,x1 into bf16 hi word + bf16 lo word (low16=x0, high16=x1)
__device__ __forceinline__ void split2(float x0, float x1, uint& hw, uint& lw) {
    asm("cvt.rn.bf16x2.f32 %0, %1, %2;" : "=r"(hw) : "f"(x1), "f"(x0));
    float h0 = __uint_as_float(hw << 16);
    float h1 = __uint_as_float(hw & 0xFFFF0000u);
    float l0 = x0 - h0, l1 = x1 - h1;
    asm("cvt.rn.bf16x2.f32 %0, %1, %2;" : "=r"(lw) : "f"(l1), "f"(l0));
}
// reconstruct 2 floats from hi/lo words
__device__ __forceinline__ float2 recon(uint hi, uint lo) {
    return make_float2(__uint_as_float(hi << 16) + __uint_as_float(lo << 16),
                       __uint_as_float(hi & 0xFFFF0000u) + __uint_as_float(lo & 0xFFFF0000u));
}
// pack 2 floats to f16x2 word (low16 = lo)
__device__ __forceinline__ uint f2h2(float lo, float hi) {
    uint r; asm("cvt.rn.f16x2.f32 %0, %1, %2;" : "=r"(r) : "f"(hi), "f"(lo)); return r;
}
__device__ __forceinline__ float2 h2f2(uint v) {
    __half2 h = *(__half2*)&v;
    return __half22float2(h);
}
__device__ __forceinline__ uint smem_u32(const void* p) {
    uint a;
    asm("{ .reg .u64 t; cvta.to.shared.u64 t, %1; cvt.u32.u64 %0, t; }" : "=r"(a) : "l"(p));
    return a;
}
__device__ __forceinline__ void ldm4(uint* r, uint a) {
    asm volatile("ldmatrix.sync.aligned.m8n8.x4.shared.b16 {%0,%1,%2,%3}, [%4];"
                 : "=r"(r[0]), "=r"(r[1]), "=r"(r[2]), "=r"(r[3]) : "r"(a));
}
__device__ __forceinline__ void mma16816(float* c, const uint* a, uint b0, uint b1) {
    asm volatile("mma.sync.aligned.m16n8k16.row.col.f32.bf16.bf16.f32 "
                 "{%0,%1,%2,%3}, {%4,%5,%6,%7}, {%8,%9}, {%0,%1,%2,%3};"
                 : "+f"(c[0]), "+f"(c[1]), "+f"(c[2]), "+f"(c[3])
                 : "r"(a[0]), "r"(a[1]), "r"(a[2]), "r"(a[3]), "r"(b0), "r"(b1));
}
__device__ __forceinline__ void mma8(float c[2][4][4], const uint* af, const uint* b8) {
#pragma unroll
    for (int i = 0; i < 2; i++) {
        const uint* a = af + i * 4;
        mma16816(c[i][0], a, b8[0], b8[2]);
        mma16816(c[i][1], a, b8[1], b8[3]);
        mma16816(c[i][2], a, b8[4], b8[6]);
        mma16816(c[i][3], a, b8[5], b8[7]);
    }
}
__device__ __forceinline__ void red4(float* p, float a, float b, float c, float d) {
    asm volatile("red.global.add.v4.f32 [%0], {%1, %2, %3, %4};"
                 :: "l"(p), "f"(a), "f"(b), "f"(c), "f"(d) : "memory");
}
__device__ __forceinline__ void cpa16(uint dst, const void* src) {
    asm volatile("cp.async.cg.shared.global [%0], [%1], 16;" :: "r"(dst), "l"(src));
}
#define CP_COMMIT asm volatile("cp.async.commit_group;" ::: "memory")
#define CP_WAIT0  asm volatile("cp.async.wait_group 0;" ::: "memory")
#define CP_WAIT1  asm volatile("cp.async.wait_group 1;" ::: "memory")

// issue one 128-row tile copy (pre-split rows: 32 hi words + 32 lo words = 256B)
__device__ __forceinline__ void issue_tile(const uint* __restrict__ x, long long n,
                                           long long base, uint sA, int tid) {
    for (int t = tid; t < 2048; t += 256) {
        int row = t >> 4, c = t & 15;
        long long gr = base + row;
        if (gr >= n) gr = n - 1;
        cpa16(sA + row * 272 + c * 16, x + gr * 64 + c * 4);
    }
}

// ---------------- scratch ----------------
// features stored pre-split: [row] = 32 hi-bf16 words, 32 lo-bf16 words
__device__ uint   g_h[50000 * HID];
__device__ uint   g_e[500000 * HID];
__device__ uint   g_l[800000 * HID];
// projection intermediates in fp16 (single-producer single-consumer scratch)
__device__ __half g_A[MAXN * HID];
__device__ __half g_B[MAXN * HID];
__device__ __half g_D[MAXN * HID];
__device__ __half g_E[MAXN * HID];
__device__ __half g_C[MAXE * HID];
__device__ float  g_accsh[MAXN * HID];
__device__ float  g_accs[MAXN * HID];
__device__ int    g_off[2048];

// ---------------- stream/event resources ----------------
static cudaStream_t g_s2 = 0;
static cudaEvent_t g_evA = 0, g_evB = 0;
static struct StreamInit {
    StreamInit() {
        if (cudaStreamCreateWithFlags(&g_s2, cudaStreamNonBlocking) != cudaSuccess) { g_s2 = 0; return; }
        if (cudaEventCreateWithFlags(&g_evA, cudaEventDisableTiming) != cudaSuccess) { g_s2 = 0; return; }
        if (cudaEventCreateWithFlags(&g_evB, cudaEventDisableTiming) != cudaSuccess) { g_s2 = 0; return; }
    }
} g_stream_init;

// ---------------- misc kernels ----------------

__global__ void embed_kernel(const int* __restrict__ an,
                             const float* __restrict__ emb, int n) {
    int i = blockIdx.x * blockDim.x + threadIdx.x;
    if (i < n * 32) {
        int row = i >> 5, w = i & 31;
        float2 v = *(const float2*)(emb + an[row] * 64 + 2 * w);
        uint hw, lw;
        split2(v.x, v.y, hw, lw);
        g_h[(size_t)row * 64 + w] = hw;
        g_h[(size_t)row * 64 + 32 + w] = lw;
    }
}

__global__ void rbf_kernel(const float* __restrict__ x, const float* __restrict__ W,
                           const float* __restrict__ bias, uint* __restrict__ out,
                           int n, int bins, float vmin, float step, float gamma) {
    __shared__ float phi[8 * 80];
    __shared__ float xs[8];
    int tx = threadIdx.x & 31, ez = threadIdx.x >> 5;
    ull bp = *(const ull*)(bias + 2 * tx);
    for (int base = blockIdx.x * 8; base < n; base += gridDim.x * 8) {
        __syncthreads();
        if (threadIdx.x < 8)
            xs[threadIdx.x] = (base + threadIdx.x < n) ? x[base + threadIdx.x] : 0.f;
        __syncthreads();
        for (int idx = threadIdx.x; idx < 8 * bins; idx += 256) {
            int ee = idx / bins, k = idx - ee * bins;
            float dd = xs[ee] - (vmin + k * step);
            phi[idx] = __expf(-gamma * dd * dd);
        }
        __syncthreads();
        int eid = base + ez;
        if (eid < n) {
            ull acc = bp;
            for (int k = 0; k < bins; k++) {
                float p = phi[ez * bins + k];
                fma2(acc, pack2(p, p), __ldg((const ull*)(W + k * HID + 2 * tx)));
            }
            float x0, x1;
            unpack2(acc, x0, x1);
            uint hw, lw;
            split2(x0, x1, hw, lw);
            out[(size_t)eid * 64 + tx] = hw;
            out[(size_t)eid * 64 + 32 + tx] = lw;
        }
    }
}

// Per-edge epilogue. Half-warp per edge, 4 cols per lane, red.v4 atomics.
// C/D/E/B tables in fp16 (8B gathers per lane).
__global__ void edge2_kernel(const int* __restrict__ src, const int* __restrict__ dst,
                             uint* __restrict__ e, int E, int write_e) {
    int lane = threadIdx.x & 31;
    int half = lane >> 4, qx = lane & 15;
    long long gw = (blockIdx.x * blockDim.x + threadIdx.x) >> 5;
    long long nw = (gridDim.x * blockDim.x) >> 5;
    for (long long p = gw; 2 * p < E; p += nw) {
        long long eid = 2 * p + half;
        if (eid >= E) continue;
        int s = __ldg(src + eid);
        int d = __ldg(dst + eid);
        size_t fo = (size_t)eid * 64 + qx * 4;
        size_t so = (size_t)s * 64 + qx * 4;
        size_t dofs = (size_t)d * 64 + qx * 4;
        uint2 cw = __ldg((const uint2*)(g_C + fo));
        uint2 dw = __ldg((const uint2*)(g_D + so));
        uint2 ew = __ldg((const uint2*)(g_E + dofs));
        uint2 bw = __ldg((const uint2*)(g_B + so));
        float2 ce01 = h2f2(cw.x), ce23 = h2f2(cw.y);
        float2 dh01 = h2f2(dw.x), dh23 = h2f2(dw.y);
        float2 eh01 = h2f2(ew.x), eh23 = h2f2(ew.y);
        float2 bh01 = h2f2(bw.x), bh23 = h2f2(bw.y);
        float en0 = dh01.x + eh01.x + ce01.x;
        float en1 = dh01.y + eh01.y + ce01.y;
        float en2 = dh23.x + eh23.x + ce23.x;
        float en3 = dh23.y + eh23.y + ce23.y;
        float sg0 = 1.f / (1.f + __expf(-en0));
        float sg1 = 1.f / (1.f + __expf(-en1));
        float sg2 = 1.f / (1.f + __expf(-en2));
        float sg3 = 1.f / (1.f + __expf(-en3));
        red4(g_accsh + dofs, bh01.x * sg0, bh01.y * sg1, bh23.x * sg2, bh23.y * sg3);
        red4(g_accs + dofs, sg0, sg1, sg2, sg3);
        if (write_e) {
            size_t eu = (size_t)eid * 64 + 2 * qx;
            uint2 hi = *(uint2*)(e + eu);
            uint2 lo = *(uint2*)(e + eu + 32);
            float2 a = recon(hi.x, lo.x);
            float2 b = recon(hi.y, lo.y);
            a.x += en0 * sg0; a.y += en1 * sg1;
            b.x += en2 * sg2; b.y += en3 * sg3;
            split2(a.x, a.y, hi.x, lo.x);
            split2(b.x, b.y, hi.y, lo.y);
            *(uint2*)(e + eu) = hi;
            *(uint2*)(e + eu + 32) = lo;
        }
    }
}

__global__ void node_kernel(uint* __restrict__ h, int n) {
    int i = blockIdx.x * blockDim.x + threadIdx.x;
    if (i < n * 32) {
        int row = i >> 5, w = i & 31;
        size_t fo = (size_t)row * 64 + 2 * w;
        float2 A = h2f2(*(const uint*)(g_A + fo));
        float2 sh = *(const float2*)(g_accsh + fo);
        float2 sS = *(const float2*)(g_accs + fo);
        float hn0 = A.x + sh.x / (sS.x + 1e-6f);
        float hn1 = A.y + sh.y / (sS.y + 1e-6f);
        size_t hu = (size_t)row * 64 + w;
        uint hi = h[hu], lo = h[hu + 32];
        float2 hv = recon(hi, lo);
        hv.x += hn0 / (1.f + __expf(-hn0));
        hv.y += hn1 / (1.f + __expf(-hn1));
        split2(hv.x, hv.y, hi, lo);
        h[hu] = hi;
        h[hu + 32] = lo;
    }
}

__global__ void offsets_kernel(const int* __restrict__ len, int Bc) {
    if (threadIdx.x == 0 && blockIdx.x == 0) {
        int o = 0;
        for (int b = 0; b < Bc && b < 2048; b++) { g_off[b] = o; o += len[b]; }
    }
}

// Fast FC+reconstruct for TH==256: persistent, fcW column cached in registers.
__global__ void __launch_bounds__(256) out2_kernel(
    const uint* __restrict__ h, const float* __restrict__ fcW,
    const float* __restrict__ fcb, const int* __restrict__ len,
    float* __restrict__ out, int n_nodes, int Bc, int L, int with_mask) {
    __shared__ float hsh[HID];
    int tid = threadIdx.x;
    float w[64];
#pragma unroll
    for (int k = 0; k < 64; k++) w[k] = __ldg(fcW + k * 256 + tid);
    float bcol = __ldg(fcb + tid);
    int total = Bc * L;
    for (int row = blockIdx.x; row < total; row += gridDim.x) {
        int b = row / L, j = row - b * L;
        int lenb = __ldg(len + b);
        size_t ro = (size_t)row * 256;
        if (with_mask && tid == 0)
            out[(size_t)Bc * L * 256 + row] = (j < lenb) ? 1.f : 0.f;
        if (j >= lenb) { out[ro + tid] = 0.f; continue; }  // block-uniform branch
        int node = g_off[b] + j;
        if (node >= n_nodes) node = n_nodes - 1;
        if (node < 0) node = 0;
        __syncthreads();
        if (tid < 32) {
            uint hi = h[(size_t)node * 64 + tid];
            uint lo = h[(size_t)node * 64 + 32 + tid];
            float2 v = recon(hi, lo);
            hsh[2 * tid] = v.x;
            hsh[2 * tid + 1] = v.y;
        }
        __syncthreads();
        float acc = bcol;
#pragma unroll
        for (int k = 0; k < 64; k++) acc = fmaf(hsh[k], w[k], acc);
        out[ro + tid] = acc;
    }
}

// Generic fallback (any TH)
__global__ void out_kernel(const uint* __restrict__ h, const float* __restrict__ fcW,
                           const float* __restrict__ fcb, const int* __restrict__ len,
                           float* __restrict__ out, int n_nodes, int Bc, int L, int TH,
                           int with_mask) {
    __shared__ float hsh[HID];
    int row = blockIdx.x;
    int b = row / L, j = row - b * L;
    int lenb = len[b];
    int m = (j < lenb) ? 1 : 0;
    if (with_mask && threadIdx.x == 0)
        out[(size_t)Bc * L * TH + row] = (float)m;
    size_t ro = (size_t)row * TH;
    if (!m) {
        for (int t = threadIdx.x; t < TH; t += blockDim.x) out[ro + t] = 0.f;
        return;
    }
    int node = g_off[b] + j;
    if (node >= n_nodes) node = n_nodes - 1;
    if (node < 0) node = 0;
    if (threadIdx.x < 32) {
        uint hi = h[(size_t)node * 64 + threadIdx.x];
        uint lo = h[(size_t)node * 64 + 32 + threadIdx.x];
        float2 v = recon(hi, lo);
        hsh[2 * threadIdx.x] = v.x;
        hsh[2 * threadIdx.x + 1] = v.y;
    }
    __syncthreads();
    for (int t = threadIdx.x; t < TH; t += blockDim.x) {
        float acc = fcb[t];
#pragma unroll
        for (int k = 0; k < HID; k++)
            acc = fmaf(hsh[k], __ldg(fcW + k * TH + t), acc);
        out[ro + t] = acc;
    }
}

// ---------------- node-side 4-matrix HMMA GEMM ----------------
// Single A buffer; afr hoisted to regs right after arrival, then next tile's
// cp.async overlaps zacc + compute. o0..o3 = x @ W{0,1,3,4} + b (fp16 out).
__global__ void __launch_bounds__(256, 2) gemm_mma(
    const uint* __restrict__ x, const float* __restrict__ Wf,
    const float* __restrict__ bf,
    __half* o0, __half* o1, __half* o2, __half* o3,
    int n, int zacc) {
    extern __shared__ __align__(16) char sm[];
    const int A_OFF = 1024;
    const int B_OFF = A_OFF + 128 * 272;
    float* biass = (float*)sm;
    int tid = threadIdx.x, lane = tid & 31, wid = tid >> 5;
    int wr = wid >> 1, wc = wid & 1;
    __half* outp[4] = {o0, o1, o2, o3};
    const int msel[4] = {0, 1, 3, 4};

    for (int t = tid; t < 4 * 512; t += 256) {
        int m = t >> 9, r = t & 511, nn = r >> 3, q = r & 7;
        const float* Wm = Wf + msel[m] * 4096;
        uint hw[4], lw[4];
#pragma unroll
        for (int i = 0; i < 4; i++) {
            int k = q * 8 + 2 * i;
            split2(__ldg(Wm + k * 64 + nn), __ldg(Wm + (k + 1) * 64 + nn), hw[i], lw[i]);
        }
        char* brow = sm + B_OFF + (m * 64 + nn) * 272;
        *(uint4*)(brow + q * 16) = make_uint4(hw[0], hw[1], hw[2], hw[3]);
        *(uint4*)(brow + 128 + q * 16) = make_uint4(lw[0], lw[1], lw[2], lw[3]);
    }
    for (int t = tid; t < 4 * 64; t += 256)
        biass[t] = bf[msel[t >> 6] * 64 + (t & 63)];

    uint sA = smem_u32(sm + A_OFF);
    uint aBase = sA + (wr * 32 + (lane & 15)) * 272 + ((lane & 16) ? 16 : 0);
    uint bBase = smem_u32(sm + B_OFF) + (lane & 15) * 272 + ((lane & 16) ? 16 : 0);
    int cq = 2 * (lane & 3), rrow = lane >> 2;

    long long step = (long long)gridDim.x * 128;
    long long base0 = (long long)blockIdx.x * 128;
    if (base0 < n) issue_tile(x, n, base0, sA, tid);
    CP_COMMIT;

    for (long long base = base0; base < n; base += step) {
        CP_WAIT0;
        __syncthreads();
        // hoist ALL distinct A fragments; A smem dead afterwards
        uint afr[8][8];
#pragma unroll
        for (int d = 0; d < 8; d++) {
            ldm4(&afr[d][0], aBase + d * 32);
            ldm4(&afr[d][4], aBase + 16 * 272 + d * 32);
        }
        __syncthreads();
        long long nxt = base + step;
        if (nxt < n) issue_tile(x, n, nxt, sA, tid);
        CP_COMMIT;

        if (zacc) {
            float4 z = make_float4(0.f, 0.f, 0.f, 0.f);
            for (int t = tid; t < 128 * 16; t += 256) {
                long long r = base + (t >> 4);
                if (r < n) {
                    int c = (t & 15) * 4;
                    *(float4*)(g_accsh + r * 64 + c) = z;
                    *(float4*)(g_accs + r * 64 + c) = z;
                }
            }
        }

        for (int cb = 0; cb < 4; cb++) {
            float c[2][4][4];
#pragma unroll
            for (int j = 0; j < 4; j++) {
                float b0v = biass[cb * 64 + wc * 32 + j * 8 + cq];
                float b1v = biass[cb * 64 + wc * 32 + j * 8 + cq + 1];
#pragma unroll
                for (int i = 0; i < 2; i++) {
                    c[i][j][0] = b0v; c[i][j][1] = b1v;
                    c[i][j][2] = b0v; c[i][j][3] = b1v;
                }
            }
            uint bMat = bBase + (cb * 64 + wc * 32) * 272;
#pragma unroll
            for (int d = 0; d < 4; d++) {
                uint bh[8], bl[8];
                ldm4(&bh[0], bMat + d * 32);
                ldm4(&bh[4], bMat + 16 * 272 + d * 32);
                mma8(c, afr[d], bh);      // Ahi·Bhi
                mma8(c, afr[d + 4], bh);  // Alo·Bhi
                ldm4(&bl[0], bMat + 128 + d * 32);
                ldm4(&bl[4], bMat + 16 * 272 + 128 + d * 32);
                mma8(c, afr[d], bl);      // Ahi·Blo
            }
            __half* op = outp[cb];
#pragma unroll
            for (int i = 0; i < 2; i++) {
                long long r0 = base + wr * 32 + i * 16 + rrow;
#pragma unroll
                for (int j = 0; j < 4; j++) {
                    int col = wc * 32 + j * 8 + cq;
                    if (r0 < n)
                        *(uint*)(op + r0 * 64 + col) = f2h2(c[i][j][0], c[i][j][1]);
                    if (r0 + 8 < n)
                        *(uint*)(op + (r0 + 8) * 64 + col) = f2h2(c[i][j][2], c[i][j][3]);
                }
            }
        }
    }
}

// ---------------- Ce HMMA GEMM (B hoisted, double-buffered A) ----------------
// g_C = x @ W2 + b2 (fp16 out)
__global__ void __launch_bounds__(256, 2) gemmC_mma(
    const uint* __restrict__ x, const float* __restrict__ W2,
    const float* __restrict__ b2, __half* __restrict__ out, int n) {
    extern __shared__ __align__(16) char sm[];
    const int A0_OFF = 1024;
    const int A1_OFF = 1024 + 128 * 272;
    const int B_OFF = A1_OFF;  // W staged temporarily in buf1
    float* biass = (float*)sm;
    int tid = threadIdx.x, lane = tid & 31, wid = tid >> 5;
    int wr = wid >> 1, wc = wid & 1;

    for (int t = tid; t < 512; t += 256) {
        int nn = t >> 3, q = t & 7;
        uint hw[4], lw[4];
#pragma unroll
        for (int i = 0; i < 4; i++) {
            int k = q * 8 + 2 * i;
            split2(__ldg(W2 + k * 64 + nn), __ldg(W2 + (k + 1) * 64 + nn), hw[i], lw[i]);
        }
        char* brow = sm + B_OFF + nn * 272;
        *(uint4*)(brow + q * 16) = make_uint4(hw[0], hw[1], hw[2], hw[3]);
        *(uint4*)(brow + 128 + q * 16) = make_uint4(lw[0], lw[1], lw[2], lw[3]);
    }
    if (tid < 64) biass[tid] = b2[tid];
    __syncthreads();

    uint sA0 = smem_u32(sm + A0_OFF);
    uint sA1 = smem_u32(sm + A1_OFF);
    uint frag = ((lane & 15) * 272) + ((lane & 16) ? 16 : 0);
    uint bMat = smem_u32(sm + B_OFF) + frag + (wc * 32) * 272;
    uint aB0 = sA0 + (wr * 32) * 272 + frag;
    uint aB1 = sA1 + (wr * 32) * 272 + frag;
    int cq = 2 * (lane & 3), rrow = lane >> 2;

    // hoist ALL B fragments: d 0..3 = hi k-steps, 4..7 = lo k-steps
    uint bfr[8][8];
#pragma unroll
    for (int d = 0; d < 8; d++) {
        ldm4(&bfr[d][0], bMat + d * 32);
        ldm4(&bfr[d][4], bMat + 16 * 272 + d * 32);
    }
    float bc[4][2];
#pragma unroll
    for (int j = 0; j < 4; j++) {
        bc[j][0] = biass[wc * 32 + j * 8 + cq];
        bc[j][1] = biass[wc * 32 + j * 8 + cq + 1];
    }
    __syncthreads();  // all warps done reading W smem before buf1 reuse

    long long step = (long long)gridDim.x * 128;
    long long base0 = (long long)blockIdx.x * 128;
    if (base0 < n) issue_tile(x, n, base0, sA0, tid);
    CP_COMMIT;

    int pb = 0;
    for (long long base = base0; base < n; base += step) {
        long long nxt = base + step;
        if (nxt < n) issue_tile(x, n, nxt, pb ? sA0 : sA1, tid);
        CP_COMMIT;
        if (nxt < n) { CP_WAIT1; } else { CP_WAIT0; }
        __syncthreads();

        uint aBase = pb ? aB1 : aB0;
        float c[2][4][4];
#pragma unroll
        for (int i = 0; i < 2; i++)
#pragma unroll
            for (int j = 0; j < 4; j++) {
                c[i][j][0] = bc[j][0]; c[i][j][1] = bc[j][1];
                c[i][j][2] = bc[j][0]; c[i][j][3] = bc[j][1];
            }
#pragma unroll
        for (int d = 0; d < 4; d++) {
            uint af[8];
            ldm4(&af[0], aBase + d * 32);
            ldm4(&af[4], aBase + 16 * 272 + d * 32);
            mma8(c, af, bfr[d]);       // Ahi·Bhi
            mma8(c, af, bfr[d + 4]);   // Ahi·Blo
        }
#pragma unroll
        for (int d = 0; d < 4; d++) {
            uint af[8];
            ldm4(&af[0], aBase + 128 + d * 32);
            ldm4(&af[4], aBase + 16 * 272 + 128 + d * 32);
            mma8(c, af, bfr[d]);       // Alo·Bhi
        }
#pragma unroll
        for (int i = 0; i < 2; i++) {
            long long r0 = base + wr * 32 + i * 16 + rrow;
#pragma unroll
            for (int j = 0; j < 4; j++) {
                int col = wc * 32 + j * 8 + cq;
                if (r0 < n)
                    *(uint*)(out + r0 * 64 + col) = f2h2(c[i][j][0], c[i][j][1]);
                if (r0 + 8 < n)
                    *(uint*)(out + (r0 + 8) * 64 + col) = f2h2(c[i][j][2], c[i][j][3]);
            }
        }
        __syncthreads();  // compute done before this buffer is overwritten
        pb ^= 1;
    }
}

// ---------------- host ----------------

extern "C" void kernel_launch(void* const* d_in, const int* in_sizes, int n_in,
                              void* d_out, int out_size) {
    const int*   an   = (const int*)d_in[0];
    const int*   src  = (const int*)d_in[1];
    const int*   dst  = (const int*)d_in[2];
    const int*   lsrc = (const int*)d_in[3];
    const int*   ldst = (const int*)d_in[4];
    const float* dist = (const float*)d_in[5];
    const float* ang  = (const float*)d_in[6];
    const int*   clen = (const int*)d_in[7];
    const float* emb  = (const float*)d_in[8];
    const float* eW   = (const float*)d_in[9];
    const float* eb   = (const float*)d_in[10];
    const float* aW   = (const float*)d_in[11];
    const float* ab   = (const float*)d_in[12];
    const float* Wg   = (const float*)d_in[13];
    const float* bg   = (const float*)d_in[14];
    const float* fcW  = (const float*)d_in[15];
    const float* fcb  = (const float*)d_in[16];

    int n_nodes = in_sizes[0];
    int n_edges = in_sizes[1];
    int n_lg    = in_sizes[3];
    int Bc      = in_sizes[7];
    int rbf_d   = in_sizes[9] / HID;
    int rbf_t   = in_sizes[11] / HID;
    int TH      = in_sizes[15] / HID;

    uint *p_h, *p_e, *p_l;
    __half *p_C, *p_A, *p_B, *p_D, *p_E;
    cudaGetSymbolAddress((void**)&p_h, g_h);
    cudaGetSymbolAddress((void**)&p_e, g_e);
    cudaGetSymbolAddress((void**)&p_l, g_l);
    cudaGetSymbolAddress((void**)&p_C, g_C);
    cudaGetSymbolAddress((void**)&p_A, g_A);
    cudaGetSymbolAddress((void**)&p_B, g_B);
    cudaGetSymbolAddress((void**)&p_D, g_D);
    cudaGetSymbolAddress((void**)&p_E, g_E);

    const int SM_G4 = 1024 + 128 * 272 + 4 * 64 * 272;  // 105472
    const int SM_G1 = 1024 + 2 * 128 * 272;             // 70656
    cudaFuncSetAttribute(gemm_mma, cudaFuncAttributeMaxDynamicSharedMemorySize, SM_G4);
    cudaFuncSetAttribute(gemmC_mma, cudaFuncAttributeMaxDynamicSharedMemorySize, SM_G1);

    long long per = (long long)out_size / Bc;
    int L, with_mask;
    if (per % (TH + 1) == 0) { L = (int)(per / (TH + 1)); with_mask = 1; }
    else                     { L = (int)(per / TH);       with_mask = 0; }

    const int GS = 148 * 8;
    bool par = (g_s2 != 0);
    cudaStream_t s2 = par ? g_s2 : (cudaStream_t)0;

    // fork: rbf(angle) on s2 ; embed + rbf(dist) on 0
    if (par) {
        cudaEventRecord(g_evA, 0);
        cudaStreamWaitEvent(g_s2, g_evA, 0);
    }
    rbf_kernel<<<GS, 256, 0, s2>>>(ang, aW, ab, p_l, n_lg, rbf_t,
                                   -1.f, 2.f / (rbf_t - 1), (rbf_t - 1) / 2.f);
    embed_kernel<<<(n_nodes * 32 + 255) / 256, 256>>>(an, emb, n_nodes);
    rbf_kernel<<<GS, 256>>>(dist, eW, eb, p_e, n_edges, rbf_d,
                            0.f, 8.f / (rbf_d - 1), (rbf_d - 1) / 8.f);
    if (par) {
        cudaEventRecord(g_evB, g_s2);
        cudaStreamWaitEvent((cudaStream_t)0, g_evB, 0);
    }

    struct GcnArgs { const int* s; const int* d; int n; int E; uint* hb; uint* ebuf; int layer; int we; };
    GcnArgs seq[6] = {
        { src,  dst,  n_nodes, n_edges, p_h, p_e, 0, 1 },
        { lsrc, ldst, n_edges, n_lg,    p_e, p_l, 1, 1 },
        { src,  dst,  n_nodes, n_edges, p_h, p_e, 2, 1 },
        { lsrc, ldst, n_edges, n_lg,    p_e, p_l, 3, 1 },
        { src,  dst,  n_nodes, n_edges, p_h, p_e, 4, 0 },
        { src,  dst,  n_nodes, n_edges, p_h, p_e, 5, 0 },
    };
    for (int i = 0; i < 6; i++) {
        const GcnArgs& a = seq[i];
        const float* Wl = Wg + (size_t)a.layer * 5 * 4096;
        const float* bl = bg + (size_t)a.layer * 5 * 64;
        int t4 = (a.n + 127) / 128;
        int t1 = (a.E + 127) / 128;
        // fork: gemmC on s2 concurrent with gemm_mma on 0
        if (par) {
            cudaEventRecord(g_evA, 0);
            cudaStreamWaitEvent(g_s2, g_evA, 0);
        }
        gemmC_mma<<<min(296, t1), 256, SM_G1, s2>>>(a.ebuf, Wl + 2 * 4096,
                                                    bl + 2 * 64, p_C, a.E);
        gemm_mma<<<min(296, t4), 256, SM_G4>>>(a.hb, Wl, bl,
                                               p_A, p_B, p_D, p_E, a.n, 1);
        if (par) {
            cudaEventRecord(g_evB, g_s2);
            cudaStreamWaitEvent((cudaStream_t)0, g_evB, 0);
        }
        edge2_kernel<<<GS, 256>>>(a.s, a.d, a.ebuf, a.E, a.we);
        node_kernel<<<(a.n * 32 + 255) / 256, 256>>>(a.hb, a.n);
    }

    offsets_kernel<<<1, 32>>>(clen, Bc);
    if (TH == 256) {
        out2_kernel<<<592, 256>>>(p_h, fcW, fcb, clen, (float*)d_out,
                                  n_nodes, Bc, L, with_mask);
    } else {
        out_kernel<<<Bc * L, 256>>>(p_h, fcW, fcb, clen, (float*)d_out,
                                    n_nodes, Bc, L, TH, with_mask);
    }
}

// round 17
// speedup vs baseline: 1.4495x; 1.4495x over previous
#include <cuda_runtime.h>
#include <cuda_fp16.h>

#define HID 64
#define MAXN 500000
#define MAXE 800000

typedef unsigned long long ull;
typedef unsigned int uint;

__device__ __forceinline__ ull pack2(float lo, float hi) {
    ull r; asm("mov.b64 %0, {%1,%2};" : "=l"(r) : "f"(lo), "f"(hi)); return r;
}
__device__ __forceinline__ void unpack2(ull v, float& lo, float& hi) {
    asm("mov.b64 {%0,%1}, %2;" : "=f"(lo), "=f"(hi) : "l"(v));
}
__device__ __forceinline__ void fma2(ull& d, ull a, ull b) {
    asm("fma.rn.f32x2 %0, %1, %2, %0;" : "+l"(d) : "l"(a), "l"(b));
}
// split floats x0,x1 into bf16 hi word + bf16 lo word (low16=x0, high16=x1)
__device__ __forceinline__ void split2(float x0, float x1, uint& hw, uint& lw) {
    asm("cvt.rn.bf16x2.f32 %0, %1, %2;" : "=r"(hw) : "f"(x1), "f"(x0));
    float h0 = __uint_as_float(hw << 16);
    float h1 = __uint_as_float(hw & 0xFFFF0000u);
    float l0 = x0 - h0, l1 = x1 - h1;
    asm("cvt.rn.bf16x2.f32 %0, %1, %2;" : "=r"(lw) : "f"(l1), "f"(l0));
}
// reconstruct 2 floats from hi/lo words
__device__ __forceinline__ float2 recon(uint hi, uint lo) {
    return make_float2(__uint_as_float(hi << 16) + __uint_as_float(lo << 16),
                       __uint_as_float(hi & 0xFFFF0000u) + __uint_as_float(lo & 0xFFFF0000u));
}
// pack 2 floats to f16x2 word (low16 = lo)
__device__ __forceinline__ uint f2h2(float lo, float hi) {
    uint r; asm("cvt.rn.f16x2.f32 %0, %1, %2;" : "=r"(r) : "f"(hi), "f"(lo)); return r;
}
__device__ __forceinline__ float2 h2f2(uint v) {
    __half2 h = *(__half2*)&v;
    return __half22float2(h);
}
__device__ __forceinline__ uint smem_u32(const void* p) {
    uint a;
    asm("{ .reg .u64 t; cvta.to.shared.u64 t, %1; cvt.u32.u64 %0, t; }" : "=r"(a) : "l"(p));
    return a;
}
__device__ __forceinline__ void ldm4(uint* r, uint a) {
    asm volatile("ldmatrix.sync.aligned.m8n8.x4.shared.b16 {%0,%1,%2,%3}, [%4];"
                 : "=r"(r[0]), "=r"(r[1]), "=r"(r[2]), "=r"(r[3]) : "r"(a));
}
__device__ __forceinline__ void mma16816(float* c, const uint* a, uint b0, uint b1) {
    asm volatile("mma.sync.aligned.m16n8k16.row.col.f32.bf16.bf16.f32 "
                 "{%0,%1,%2,%3}, {%4,%5,%6,%7}, {%8,%9}, {%0,%1,%2,%3};"
                 : "+f"(c[0]), "+f"(c[1]), "+f"(c[2]), "+f"(c[3])
                 : "r"(a[0]), "r"(a[1]), "r"(a[2]), "r"(a[3]), "r"(b0), "r"(b1));
}
__device__ __forceinline__ void mma8(float c[2][4][4], const uint* af, const uint* b8) {
#pragma unroll
    for (int i = 0; i < 2; i++) {
        const uint* a = af + i * 4;
        mma16816(c[i][0], a, b8[0], b8[2]);
        mma16816(c[i][1], a, b8[1], b8[3]);
        mma16816(c[i][2], a, b8[4], b8[6]);
        mma16816(c[i][3], a, b8[5], b8[7]);
    }
}
__device__ __forceinline__ void red4(float* p, float a, float b, float c, float d) {
    asm volatile("red.global.add.v4.f32 [%0], {%1, %2, %3, %4};"
                 :: "l"(p), "f"(a), "f"(b), "f"(c), "f"(d) : "memory");
}
__device__ __forceinline__ void cpa16(uint dst, const void* src) {
    asm volatile("cp.async.cg.shared.global [%0], [%1], 16;" :: "r"(dst), "l"(src));
}
#define CP_COMMIT asm volatile("cp.async.commit_group;" ::: "memory")
#define CP_WAIT0  asm volatile("cp.async.wait_group 0;" ::: "memory")
#define CP_WAIT1  asm volatile("cp.async.wait_group 1;" ::: "memory")

// issue one 128-row tile copy (pre-split rows: 32 hi words + 32 lo words = 256B)
__device__ __forceinline__ void issue_tile(const uint* __restrict__ x, long long n,
                                           long long base, uint sA, int tid) {
    for (int t = tid; t < 2048; t += 256) {
        int row = t >> 4, c = t & 15;
        long long gr = base + row;
        if (gr >= n) gr = n - 1;
        cpa16(sA + row * 272 + c * 16, x + gr * 64 + c * 4);
    }
}

// ---------------- scratch ----------------
// features stored pre-split: [row] = 32 hi-bf16 words, 32 lo-bf16 words
__device__ uint   g_h[50000 * HID];
__device__ uint   g_e[500000 * HID];
__device__ uint   g_l[800000 * HID];
// projection intermediates in fp16 (single-producer single-consumer scratch)
__device__ __half g_A[MAXN * HID];
__device__ __half g_B[MAXN * HID];
__device__ __half g_D[MAXN * HID];
__device__ __half g_E[MAXN * HID];
__device__ __half g_C[MAXE * HID];
__device__ float  g_accsh[MAXN * HID];
__device__ float  g_accs[MAXN * HID];
__device__ int    g_off[2048];

// ---------------- stream/event resources ----------------
static cudaStream_t g_s2 = 0;
static cudaEvent_t g_evA = 0, g_evB = 0;
static struct StreamInit {
    StreamInit() {
        if (cudaStreamCreateWithFlags(&g_s2, cudaStreamNonBlocking) != cudaSuccess) { g_s2 = 0; return; }
        if (cudaEventCreateWithFlags(&g_evA, cudaEventDisableTiming) != cudaSuccess) { g_s2 = 0; return; }
        if (cudaEventCreateWithFlags(&g_evB, cudaEventDisableTiming) != cudaSuccess) { g_s2 = 0; return; }
    }
} g_stream_init;

// ---------------- misc kernels ----------------

__global__ void embed_kernel(const int* __restrict__ an,
                             const float* __restrict__ emb, int n) {
    int i = blockIdx.x * blockDim.x + threadIdx.x;
    if (i < n * 32) {
        int row = i >> 5, w = i & 31;
        float2 v = *(const float2*)(emb + an[row] * 64 + 2 * w);
        uint hw, lw;
        split2(v.x, v.y, hw, lw);
        g_h[(size_t)row * 64 + w] = hw;
        g_h[(size_t)row * 64 + 32 + w] = lw;
    }
}

__global__ void rbf_kernel(const float* __restrict__ x, const float* __restrict__ W,
                           const float* __restrict__ bias, uint* __restrict__ out,
                           int n, int bins, float vmin, float step, float gamma) {
    __shared__ float phi[8 * 80];
    __shared__ float xs[8];
    int tx = threadIdx.x & 31, ez = threadIdx.x >> 5;
    ull bp = *(const ull*)(bias + 2 * tx);
    for (int base = blockIdx.x * 8; base < n; base += gridDim.x * 8) {
        __syncthreads();
        if (threadIdx.x < 8)
            xs[threadIdx.x] = (base + threadIdx.x < n) ? x[base + threadIdx.x] : 0.f;
        __syncthreads();
        for (int idx = threadIdx.x; idx < 8 * bins; idx += 256) {
            int ee = idx / bins, k = idx - ee * bins;
            float dd = xs[ee] - (vmin + k * step);
            phi[idx] = __expf(-gamma * dd * dd);
        }
        __syncthreads();
        int eid = base + ez;
        if (eid < n) {
            ull acc = bp;
            for (int k = 0; k < bins; k++) {
                float p = phi[ez * bins + k];
                fma2(acc, pack2(p, p), __ldg((const ull*)(W + k * HID + 2 * tx)));
            }
            float x0, x1;
            unpack2(acc, x0, x1);
            uint hw, lw;
            split2(x0, x1, hw, lw);
            out[(size_t)eid * 64 + tx] = hw;
            out[(size_t)eid * 64 + 32 + tx] = lw;
        }
    }
}

// Per-edge epilogue. Half-warp per edge, 4 cols per lane, red.v4 atomics.
// C/D/E/B tables in fp16 (8B gathers per lane).
__global__ void edge2_kernel(const int* __restrict__ src, const int* __restrict__ dst,
                             uint* __restrict__ e, int E, int write_e) {
    int lane = threadIdx.x & 31;
    int half = lane >> 4, qx = lane & 15;
    long long gw = (blockIdx.x * blockDim.x + threadIdx.x) >> 5;
    long long nw = (gridDim.x * blockDim.x) >> 5;
    for (long long p = gw; 2 * p < E; p += nw) {
        long long eid = 2 * p + half;
        if (eid >= E) continue;
        int s = __ldg(src + eid);
        int d = __ldg(dst + eid);
        size_t fo = (size_t)eid * 64 + qx * 4;
        size_t so = (size_t)s * 64 + qx * 4;
        size_t dofs = (size_t)d * 64 + qx * 4;
        uint2 cw = __ldg((const uint2*)(g_C + fo));
        uint2 dw = __ldg((const uint2*)(g_D + so));
        uint2 ew = __ldg((const uint2*)(g_E + dofs));
        uint2 bw = __ldg((const uint2*)(g_B + so));
        float2 ce01 = h2f2(cw.x), ce23 = h2f2(cw.y);
        float2 dh01 = h2f2(dw.x), dh23 = h2f2(dw.y);
        float2 eh01 = h2f2(ew.x), eh23 = h2f2(ew.y);
        float2 bh01 = h2f2(bw.x), bh23 = h2f2(bw.y);
        float en0 = dh01.x + eh01.x + ce01.x;
        float en1 = dh01.y + eh01.y + ce01.y;
        float en2 = dh23.x + eh23.x + ce23.x;
        float en3 = dh23.y + eh23.y + ce23.y;
        float sg0 = 1.f / (1.f + __expf(-en0));
        float sg1 = 1.f / (1.f + __expf(-en1));
        float sg2 = 1.f / (1.f + __expf(-en2));
        float sg3 = 1.f / (1.f + __expf(-en3));
        red4(g_accsh + dofs, bh01.x * sg0, bh01.y * sg1, bh23.x * sg2, bh23.y * sg3);
        red4(g_accs + dofs, sg0, sg1, sg2, sg3);
        if (write_e) {
            size_t eu = (size_t)eid * 64 + 2 * qx;
            uint2 hi = *(uint2*)(e + eu);
            uint2 lo = *(uint2*)(e + eu + 32);
            float2 a = recon(hi.x, lo.x);
            float2 b = recon(hi.y, lo.y);
            a.x += en0 * sg0; a.y += en1 * sg1;
            b.x += en2 * sg2; b.y += en3 * sg3;
            split2(a.x, a.y, hi.x, lo.x);
            split2(b.x, b.y, hi.y, lo.y);
            *(uint2*)(e + eu) = hi;
            *(uint2*)(e + eu + 32) = lo;
        }
    }
}

__global__ void node_kernel(uint* __restrict__ h, int n) {
    int i = blockIdx.x * blockDim.x + threadIdx.x;
    if (i < n * 32) {
        int row = i >> 5, w = i & 31;
        size_t fo = (size_t)row * 64 + 2 * w;
        float2 A = h2f2(*(const uint*)(g_A + fo));
        float2 sh = *(const float2*)(g_accsh + fo);
        float2 sS = *(const float2*)(g_accs + fo);
        float hn0 = A.x + sh.x / (sS.x + 1e-6f);
        float hn1 = A.y + sh.y / (sS.y + 1e-6f);
        size_t hu = (size_t)row * 64 + w;
        uint hi = h[hu], lo = h[hu + 32];
        float2 hv = recon(hi, lo);
        hv.x += hn0 / (1.f + __expf(-hn0));
        hv.y += hn1 / (1.f + __expf(-hn1));
        split2(hv.x, hv.y, hi, lo);
        h[hu] = hi;
        h[hu + 32] = lo;
    }
}

__global__ void offsets_kernel(const int* __restrict__ len, int Bc) {
    if (threadIdx.x == 0 && blockIdx.x == 0) {
        int o = 0;
        for (int b = 0; b < Bc && b < 2048; b++) { g_off[b] = o; o += len[b]; }
    }
}

// Fast FC+reconstruct for TH==256: persistent, fcW column cached in registers.
__global__ void __launch_bounds__(256) out2_kernel(
    const uint* __restrict__ h, const float* __restrict__ fcW,
    const float* __restrict__ fcb, const int* __restrict__ len,
    float* __restrict__ out, int n_nodes, int Bc, int L, int with_mask) {
    __shared__ float hsh[HID];
    int tid = threadIdx.x;
    float w[64];
#pragma unroll
    for (int k = 0; k < 64; k++) w[k] = __ldg(fcW + k * 256 + tid);
    float bcol = __ldg(fcb + tid);
    int total = Bc * L;
    for (int row = blockIdx.x; row < total; row += gridDim.x) {
        int b = row / L, j = row - b * L;
        int lenb = __ldg(len + b);
        size_t ro = (size_t)row * 256;
        if (with_mask && tid == 0)
            out[(size_t)Bc * L * 256 + row] = (j < lenb) ? 1.f : 0.f;
        if (j >= lenb) { out[ro + tid] = 0.f; continue; }  // block-uniform branch
        int node = g_off[b] + j;
        if (node >= n_nodes) node = n_nodes - 1;
        if (node < 0) node = 0;
        __syncthreads();
        if (tid < 32) {
            uint hi = h[(size_t)node * 64 + tid];
            uint lo = h[(size_t)node * 64 + 32 + tid];
            float2 v = recon(hi, lo);
            hsh[2 * tid] = v.x;
            hsh[2 * tid + 1] = v.y;
        }
        __syncthreads();
        float acc = bcol;
#pragma unroll
        for (int k = 0; k < 64; k++) acc = fmaf(hsh[k], w[k], acc);
        out[ro + tid] = acc;
    }
}

// Generic fallback (any TH)
__global__ void out_kernel(const uint* __restrict__ h, const float* __restrict__ fcW,
                           const float* __restrict__ fcb, const int* __restrict__ len,
                           float* __restrict__ out, int n_nodes, int Bc, int L, int TH,
                           int with_mask) {
    __shared__ float hsh[HID];
    int row = blockIdx.x;
    int b = row / L, j = row - b * L;
    int lenb = len[b];
    int m = (j < lenb) ? 1 : 0;
    if (with_mask && threadIdx.x == 0)
        out[(size_t)Bc * L * TH + row] = (float)m;
    size_t ro = (size_t)row * TH;
    if (!m) {
        for (int t = threadIdx.x; t < TH; t += blockDim.x) out[ro + t] = 0.f;
        return;
    }
    int node = g_off[b] + j;
    if (node >= n_nodes) node = n_nodes - 1;
    if (node < 0) node = 0;
    if (threadIdx.x < 32) {
        uint hi = h[(size_t)node * 64 + threadIdx.x];
        uint lo = h[(size_t)node * 64 + 32 + threadIdx.x];
        float2 v = recon(hi, lo);
        hsh[2 * threadIdx.x] = v.x;
        hsh[2 * threadIdx.x + 1] = v.y;
    }
    __syncthreads();
    for (int t = threadIdx.x; t < TH; t += blockDim.x) {
        float acc = fcb[t];
#pragma unroll
        for (int k = 0; k < HID; k++)
            acc = fmaf(hsh[k], __ldg(fcW + k * TH + t), acc);
        out[ro + t] = acc;
    }
}

// ---------------- node-side 4-matrix HMMA GEMM ----------------
// Single A buffer; afr hoisted to regs right after arrival, then next tile's
// cp.async overlaps zacc + compute. o0..o3 = x @ W{0,1,3,4} + b (fp16 out).
__global__ void __launch_bounds__(256, 2) gemm_mma(
    const uint* __restrict__ x, const float* __restrict__ Wf,
    const float* __restrict__ bf,
    __half* o0, __half* o1, __half* o2, __half* o3,
    int n, int zacc) {
    extern __shared__ __align__(16) char sm[];
    const int A_OFF = 1024;
    const int B_OFF = A_OFF + 128 * 272;
    float* biass = (float*)sm;
    int tid = threadIdx.x, lane = tid & 31, wid = tid >> 5;
    int wr = wid >> 1, wc = wid & 1;
    __half* outp[4] = {o0, o1, o2, o3};
    const int msel[4] = {0, 1, 3, 4};

    for (int t = tid; t < 4 * 512; t += 256) {
        int m = t >> 9, r = t & 511, nn = r >> 3, q = r & 7;
        const float* Wm = Wf + msel[m] * 4096;
        uint hw[4], lw[4];
#pragma unroll
        for (int i = 0; i < 4; i++) {
            int k = q * 8 + 2 * i;
            split2(__ldg(Wm + k * 64 + nn), __ldg(Wm + (k + 1) * 64 + nn), hw[i], lw[i]);
        }
        char* brow = sm + B_OFF + (m * 64 + nn) * 272;
        *(uint4*)(brow + q * 16) = make_uint4(hw[0], hw[1], hw[2], hw[3]);
        *(uint4*)(brow + 128 + q * 16) = make_uint4(lw[0], lw[1], lw[2], lw[3]);
    }
    for (int t = tid; t < 4 * 64; t += 256)
        biass[t] = bf[msel[t >> 6] * 64 + (t & 63)];

    uint sA = smem_u32(sm + A_OFF);
    uint aBase = sA + (wr * 32 + (lane & 15)) * 272 + ((lane & 16) ? 16 : 0);
    uint bBase = smem_u32(sm + B_OFF) + (lane & 15) * 272 + ((lane & 16) ? 16 : 0);
    int cq = 2 * (lane & 3), rrow = lane >> 2;

    long long step = (long long)gridDim.x * 128;
    long long base0 = (long long)blockIdx.x * 128;
    if (base0 < n) issue_tile(x, n, base0, sA, tid);
    CP_COMMIT;

    for (long long base = base0; base < n; base += step) {
        CP_WAIT0;
        __syncthreads();
        // hoist ALL distinct A fragments; A smem dead afterwards
        uint afr[8][8];
#pragma unroll
        for (int d = 0; d < 8; d++) {
            ldm4(&afr[d][0], aBase + d * 32);
            ldm4(&afr[d][4], aBase + 16 * 272 + d * 32);
        }
        __syncthreads();
        long long nxt = base + step;
        if (nxt < n) issue_tile(x, n, nxt, sA, tid);
        CP_COMMIT;

        if (zacc) {
            float4 z = make_float4(0.f, 0.f, 0.f, 0.f);
            for (int t = tid; t < 128 * 16; t += 256) {
                long long r = base + (t >> 4);
                if (r < n) {
                    int c = (t & 15) * 4;
                    *(float4*)(g_accsh + r * 64 + c) = z;
                    *(float4*)(g_accs + r * 64 + c) = z;
                }
            }
        }

        for (int cb = 0; cb < 4; cb++) {
            float c[2][4][4];
#pragma unroll
            for (int j = 0; j < 4; j++) {
                float b0v = biass[cb * 64 + wc * 32 + j * 8 + cq];
                float b1v = biass[cb * 64 + wc * 32 + j * 8 + cq + 1];
#pragma unroll
                for (int i = 0; i < 2; i++) {
                    c[i][j][0] = b0v; c[i][j][1] = b1v;
                    c[i][j][2] = b0v; c[i][j][3] = b1v;
                }
            }
            uint bMat = bBase + (cb * 64 + wc * 32) * 272;
#pragma unroll
            for (int d = 0; d < 4; d++) {
                uint bh[8], bl[8];
                ldm4(&bh[0], bMat + d * 32);
                ldm4(&bh[4], bMat + 16 * 272 + d * 32);
                mma8(c, afr[d], bh);      // Ahi·Bhi
                mma8(c, afr[d + 4], bh);  // Alo·Bhi
                ldm4(&bl[0], bMat + 128 + d * 32);
                ldm4(&bl[4], bMat + 16 * 272 + 128 + d * 32);
                mma8(c, afr[d], bl);      // Ahi·Blo
            }
            __half* op = outp[cb];
#pragma unroll
            for (int i = 0; i < 2; i++) {
                long long r0 = base + wr * 32 + i * 16 + rrow;
#pragma unroll
                for (int j = 0; j < 4; j++) {
                    int col = wc * 32 + j * 8 + cq;
                    if (r0 < n)
                        *(uint*)(op + r0 * 64 + col) = f2h2(c[i][j][0], c[i][j][1]);
                    if (r0 + 8 < n)
                        *(uint*)(op + (r0 + 8) * 64 + col) = f2h2(c[i][j][2], c[i][j][3]);
                }
            }
        }
    }
}

// ---------------- Ce HMMA GEMM (B hoisted, double-buffered A) ----------------
// g_C = x @ W2 + b2 (fp16 out)
__global__ void __launch_bounds__(256, 2) gemmC_mma(
    const uint* __restrict__ x, const float* __restrict__ W2,
    const float* __restrict__ b2, __half* __restrict__ out, int n) {
    extern __shared__ __align__(16) char sm[];
    const int A0_OFF = 1024;
    const int A1_OFF = 1024 + 128 * 272;
    const int B_OFF = A1_OFF;  // W staged temporarily in buf1
    float* biass = (float*)sm;
    int tid = threadIdx.x, lane = tid & 31, wid = tid >> 5;
    int wr = wid >> 1, wc = wid & 1;

    for (int t = tid; t < 512; t += 256) {
        int nn = t >> 3, q = t & 7;
        uint hw[4], lw[4];
#pragma unroll
        for (int i = 0; i < 4; i++) {
            int k = q * 8 + 2 * i;
            split2(__ldg(W2 + k * 64 + nn), __ldg(W2 + (k + 1) * 64 + nn), hw[i], lw[i]);
        }
        char* brow = sm + B_OFF + nn * 272;
        *(uint4*)(brow + q * 16) = make_uint4(hw[0], hw[1], hw[2], hw[3]);
        *(uint4*)(brow + 128 + q * 16) = make_uint4(lw[0], lw[1], lw[2], lw[3]);
    }
    if (tid < 64) biass[tid] = b2[tid];
    __syncthreads();

    uint sA0 = smem_u32(sm + A0_OFF);
    uint sA1 = smem_u32(sm + A1_OFF);
    uint frag = ((lane & 15) * 272) + ((lane & 16) ? 16 : 0);
    uint bMat = smem_u32(sm + B_OFF) + frag + (wc * 32) * 272;
    uint aB0 = sA0 + (wr * 32) * 272 + frag;
    uint aB1 = sA1 + (wr * 32) * 272 + frag;
    int cq = 2 * (lane & 3), rrow = lane >> 2;

    // hoist ALL B fragments: d 0..3 = hi k-steps, 4..7 = lo k-steps
    uint bfr[8][8];
#pragma unroll
    for (int d = 0; d < 8; d++) {
        ldm4(&bfr[d][0], bMat + d * 32);
        ldm4(&bfr[d][4], bMat + 16 * 272 + d * 32);
    }
    float bc[4][2];
#pragma unroll
    for (int j = 0; j < 4; j++) {
        bc[j][0] = biass[wc * 32 + j * 8 + cq];
        bc[j][1] = biass[wc * 32 + j * 8 + cq + 1];
    }
    __syncthreads();  // all warps done reading W smem before buf1 reuse

    long long step = (long long)gridDim.x * 128;
    long long base0 = (long long)blockIdx.x * 128;
    if (base0 < n) issue_tile(x, n, base0, sA0, tid);
    CP_COMMIT;

    int pb = 0;
    for (long long base = base0; base < n; base += step) {
        long long nxt = base + step;
        if (nxt < n) issue_tile(x, n, nxt, pb ? sA0 : sA1, tid);
        CP_COMMIT;
        if (nxt < n) { CP_WAIT1; } else { CP_WAIT0; }
        __syncthreads();

        uint aBase = pb ? aB1 : aB0;
        float c[2][4][4];
#pragma unroll
        for (int i = 0; i < 2; i++)
#pragma unroll
            for (int j = 0; j < 4; j++) {
                c[i][j][0] = bc[j][0]; c[i][j][1] = bc[j][1];
                c[i][j][2] = bc[j][0]; c[i][j][3] = bc[j][1];
            }
#pragma unroll
        for (int d = 0; d < 4; d++) {
            uint af[8];
            ldm4(&af[0], aBase + d * 32);
            ldm4(&af[4], aBase + 16 * 272 + d * 32);
            mma8(c, af, bfr[d]);       // Ahi·Bhi
            mma8(c, af, bfr[d + 4]);   // Ahi·Blo
        }
#pragma unroll
        for (int d = 0; d < 4; d++) {
            uint af[8];
            ldm4(&af[0], aBase + 128 + d * 32);
            ldm4(&af[4], aBase + 16 * 272 + 128 + d * 32);
            mma8(c, af, bfr[d]);       // Alo·Bhi
        }
#pragma unroll
        for (int i = 0; i < 2; i++) {
            long long r0 = base + wr * 32 + i * 16 + rrow;
#pragma unroll
            for (int j = 0; j < 4; j++) {
                int col = wc * 32 + j * 8 + cq;
                if (r0 < n)
                    *(uint*)(out + r0 * 64 + col) = f2h2(c[i][j][0], c[i][j][1]);
                if (r0 + 8 < n)
                    *(uint*)(out + (r0 + 8) * 64 + col) = f2h2(c[i][j][2], c[i][j][3]);
            }
        }
        __syncthreads();  // compute done before this buffer is overwritten
        pb ^= 1;
    }
}

// ---------------- host ----------------

extern "C" void kernel_launch(void* const* d_in, const int* in_sizes, int n_in,
                              void* d_out, int out_size) {
    const int*   an   = (const int*)d_in[0];
    const int*   src  = (const int*)d_in[1];
    const int*   dst  = (const int*)d_in[2];
    const int*   lsrc = (const int*)d_in[3];
    const int*   ldst = (const int*)d_in[4];
    const float* dist = (const float*)d_in[5];
    const float* ang  = (const float*)d_in[6];
    const int*   clen = (const int*)d_in[7];
    const float* emb  = (const float*)d_in[8];
    const float* eW   = (const float*)d_in[9];
    const float* eb   = (const float*)d_in[10];
    const float* aW   = (const float*)d_in[11];
    const float* ab   = (const float*)d_in[12];
    const float* Wg   = (const float*)d_in[13];
    const float* bg   = (const float*)d_in[14];
    const float* fcW  = (const float*)d_in[15];
    const float* fcb  = (const float*)d_in[16];

    int n_nodes = in_sizes[0];
    int n_edges = in_sizes[1];
    int n_lg    = in_sizes[3];
    int Bc      = in_sizes[7];
    int rbf_d   = in_sizes[9] / HID;
    int rbf_t   = in_sizes[11] / HID;
    int TH      = in_sizes[15] / HID;

    uint *p_h, *p_e, *p_l;
    __half *p_C, *p_A, *p_B, *p_D, *p_E;
    cudaGetSymbolAddress((void**)&p_h, g_h);
    cudaGetSymbolAddress((void**)&p_e, g_e);
    cudaGetSymbolAddress((void**)&p_l, g_l);
    cudaGetSymbolAddress((void**)&p_C, g_C);
    cudaGetSymbolAddress((void**)&p_A, g_A);
    cudaGetSymbolAddress((void**)&p_B, g_B);
    cudaGetSymbolAddress((void**)&p_D, g_D);
    cudaGetSymbolAddress((void**)&p_E, g_E);

    const int SM_G4 = 1024 + 128 * 272 + 4 * 64 * 272;  // 105472
    const int SM_G1 = 1024 + 2 * 128 * 272;             // 70656
    cudaFuncSetAttribute(gemm_mma, cudaFuncAttributeMaxDynamicSharedMemorySize, SM_G4);
    cudaFuncSetAttribute(gemmC_mma, cudaFuncAttributeMaxDynamicSharedMemorySize, SM_G1);

    long long per = (long long)out_size / Bc;
    int L, with_mask;
    if (per % (TH + 1) == 0) { L = (int)(per / (TH + 1)); with_mask = 1; }
    else                     { L = (int)(per / TH);       with_mask = 0; }

    const int GS = 148 * 8;
    bool par = (g_s2 != 0);
    cudaStream_t s2 = par ? g_s2 : (cudaStream_t)0;

    // fork: rbf(angle) on s2 ; embed + rbf(dist) on 0
    if (par) {
        cudaEventRecord(g_evA, 0);
        cudaStreamWaitEvent(g_s2, g_evA, 0);
    }
    rbf_kernel<<<GS, 256, 0, s2>>>(ang, aW, ab, p_l, n_lg, rbf_t,
                                   -1.f, 2.f / (rbf_t - 1), (rbf_t - 1) / 2.f);
    embed_kernel<<<(n_nodes * 32 + 255) / 256, 256>>>(an, emb, n_nodes);
    rbf_kernel<<<GS, 256>>>(dist, eW, eb, p_e, n_edges, rbf_d,
                            0.f, 8.f / (rbf_d - 1), (rbf_d - 1) / 8.f);
    if (par) {
        cudaEventRecord(g_evB, g_s2);
        cudaStreamWaitEvent((cudaStream_t)0, g_evB, 0);
    }

    struct GcnArgs { const int* s; const int* d; int n; int E; uint* hb; uint* ebuf; int layer; int we; };
    GcnArgs seq[6] = {
        { src,  dst,  n_nodes, n_edges, p_h, p_e, 0, 1 },
        { lsrc, ldst, n_edges, n_lg,    p_e, p_l, 1, 1 },
        { src,  dst,  n_nodes, n_edges, p_h, p_e, 2, 1 },
        { lsrc, ldst, n_edges, n_lg,    p_e, p_l, 3, 1 },
        { src,  dst,  n_nodes, n_edges, p_h, p_e, 4, 0 },
        { src,  dst,  n_nodes, n_edges, p_h, p_e, 5, 0 },
    };
    for (int i = 0; i < 6; i++) {
        const GcnArgs& a = seq[i];
        const float* Wl = Wg + (size_t)a.layer * 5 * 4096;
        const float* bl = bg + (size_t)a.layer * 5 * 64;
        int t4 = (a.n + 127) / 128;
        int t1 = (a.E + 127) / 128;
        // fork: gemmC on s2 concurrent with gemm_mma on 0
        if (par) {
            cudaEventRecord(g_evA, 0);
            cudaStreamWaitEvent(g_s2, g_evA, 0);
        }
        gemmC_mma<<<min(296, t1), 256, SM_G1, s2>>>(a.ebuf, Wl + 2 * 4096,
                                                    bl + 2 * 64, p_C, a.E);
        gemm_mma<<<min(296, t4), 256, SM_G4>>>(a.hb, Wl, bl,
                                               p_A, p_B, p_D, p_E, a.n, 1);
        if (par) {
            cudaEventRecord(g_evB, g_s2);
            cudaStreamWaitEvent((cudaStream_t)0, g_evB, 0);
        }
        edge2_kernel<<<GS, 256>>>(a.s, a.d, a.ebuf, a.E, a.we);
        node_kernel<<<(a.n * 32 + 255) / 256, 256>>>(a.hb, a.n);
    }

    offsets_kernel<<<1, 32>>>(clen, Bc);
    if (TH == 256) {
        out2_kernel<<<592, 256>>>(p_h, fcW, fcb, clen, (float*)d_out,
                                  n_nodes, Bc, L, with_mask);
    } else {
        out_kernel<<<Bc * L, 256>>>(p_h, fcW, fcb, clen, (float*)d_out,
                                    n_nodes, Bc, L, TH, with_mask);
    }
}